// round 1
// baseline (speedup 1.0000x reference)
#include <cuda_runtime.h>
#include <stdint.h>

// Problem constants (shapes fixed by the benchmark: x = (32, 56, 56, 256) fp32)
#define B_     32
#define HW_    3136        // 56*56
#define C_     256
#define DIM_   802816      // HW_*C_
#define KRANK  160564u     // ceil(0.2 * 802816)
#define NBUCK  4096        // top-12-bit buckets
#define CAP    65536       // candidate capacity per sample (~9x margin over expected ~7K)

// ---------------- device scratch (static, no runtime allocation) -------------
__device__ unsigned int g_hist[B_ * NBUCK];
__device__ unsigned int g_cnt[B_];
__device__ unsigned int g_sel[B_];
__device__ unsigned int g_above[B_];
__device__ unsigned int g_ckey[B_ * CAP];
__device__ int          g_cidx[B_ * CAP];

// order-preserving key: larger float -> larger unsigned key
__device__ __forceinline__ unsigned int fkey(float f) {
    unsigned int u = __float_as_uint(f);
    return (u & 0x80000000u) ? ~u : (u | 0x80000000u);
}

// ---------------- kernel 0: zero scratch -------------------------------------
__global__ void k0_zero() {
    int total = B_ * NBUCK;
    for (int i = blockIdx.x * blockDim.x + threadIdx.x; i < total;
         i += gridDim.x * blockDim.x)
        g_hist[i] = 0u;
    if (blockIdx.x == 0 && threadIdx.x < B_) g_cnt[threadIdx.x] = 0u;
}

// ---------------- kernel 1: per-sample 4096-bucket histogram -----------------
// grid = (49, 32); each block handles 16384 contiguous floats of one sample.
__global__ void k1_hist(const float* __restrict__ x) {
    __shared__ unsigned int sh[2][NBUCK];
    const int b = blockIdx.y;
    for (int i = threadIdx.x; i < 2 * NBUCK; i += 256)
        ((unsigned int*)sh)[i] = 0u;
    __syncthreads();

    const float4* p = (const float4*)x + (size_t)b * (DIM_ / 4) + blockIdx.x * 4096;
    unsigned int* h = sh[(threadIdx.x >> 5) & 1];   // split warps across 2 copies

#pragma unroll
    for (int i = 0; i < 16; i++) {
        float4 v = p[i * 256 + threadIdx.x];
        atomicAdd(&h[fkey(v.x) >> 20], 1u);
        atomicAdd(&h[fkey(v.y) >> 20], 1u);
        atomicAdd(&h[fkey(v.z) >> 20], 1u);
        atomicAdd(&h[fkey(v.w) >> 20], 1u);
    }
    __syncthreads();

    unsigned int* gh = &g_hist[b * NBUCK];
    for (int i = threadIdx.x; i < NBUCK; i += 256) {
        unsigned int s = sh[0][i] + sh[1][i];
        if (s) atomicAdd(&gh[i], s);
    }
}

// ---------------- kernel 2: find bucket containing rank-k --------------------
// grid = 32 (one block/sample), 128 threads
__global__ void k2_select() {
    const int b = blockIdx.x;
    __shared__ unsigned int part[128];
    const unsigned int* gh = &g_hist[b * NBUCK];

    unsigned int s = 0;
#pragma unroll
    for (int j = 0; j < 32; j++)
        s += gh[(NBUCK - 1) - (threadIdx.x * 32 + j)];
    part[threadIdx.x] = s;
    __syncthreads();

    if (threadIdx.x == 0) {
        unsigned int cum = 0; int seg = 127;
        for (int t = 0; t < 128; t++) {
            if (cum + part[t] >= KRANK) { seg = t; break; }
            cum += part[t];
        }
        unsigned int c = cum, selb = 0;
        for (int j = 0; j < 32; j++) {
            unsigned int bk = (NBUCK - 1) - (seg * 32 + j);
            unsigned int hc = gh[bk];
            if (c + hc >= KRANK) { selb = bk; break; }
            c += hc;
        }
        g_sel[b]   = selb;
        g_above[b] = c;   // count strictly above selected bucket
    }
}

// ---------------- kernel 3: transpose + mask + collect candidates ------------
// grid = (98 hw-tiles, 8 c-tiles, 32 samples), 256 threads, 32x32 tile
__global__ void k3_mask(const float* __restrict__ x, float* __restrict__ out) {
    __shared__ float tile[32][33];
    const int b   = blockIdx.z;
    const int hw0 = blockIdx.x * 32;
    const int c0  = blockIdx.y * 32;
    const unsigned int sel = g_sel[b];

    const int tc = threadIdx.x & 31;
    const int tr = threadIdx.x >> 5;   // 0..7

    const float* xb = x + (size_t)b * DIM_;
#pragma unroll
    for (int i = 0; i < 4; i++) {
        int row = tr + i * 8;
        tile[row][tc] = xb[(size_t)(hw0 + row) * C_ + c0 + tc];
    }
    __syncthreads();

    float* ob = out + (size_t)b * DIM_;
#pragma unroll
    for (int i = 0; i < 4; i++) {
        int   cc = tr + i * 8;
        float v  = tile[tc][cc];
        unsigned int kk  = fkey(v);
        unsigned int t12 = kk >> 20;
        float o;
        if (t12 > sel) {
            o = v;
        } else if (t12 < sel) {
            o = 0.0f;
        } else {
            unsigned int pos = atomicAdd(&g_cnt[b], 1u);
            if (pos < CAP) {
                g_ckey[b * CAP + pos] = kk;
                g_cidx[b * CAP + pos] = (c0 + cc) * HW_ + hw0 + tc;
            }
            o = 0.0f;  // provisional; k4 rewrites kept candidates
        }
        ob[(size_t)(c0 + cc) * HW_ + hw0 + tc] = o;
    }
}

// ---------------- kernel 4: exact select within bucket + fix candidates ------
// grid = 32 (one block/sample), 256 threads
__global__ void k4_final(float* __restrict__ out) {
    const int b = blockIdx.x;
    __shared__ unsigned int h[1024];
    __shared__ unsigned int sc[256];
    __shared__ unsigned int res[3];

    const unsigned int n   = min(g_cnt[b], (unsigned int)CAP);
    const unsigned int r   = KRANK - g_above[b];  // rank within bucket (1-based)
    const unsigned int sel = g_sel[b];
    const unsigned int* ck = &g_ckey[b * CAP];

    // Phase A: histogram of bits [19:10]
    for (int i = threadIdx.x; i < 1024; i += 256) h[i] = 0u;
    __syncthreads();
    for (unsigned int i = threadIdx.x; i < n; i += 256)
        atomicAdd(&h[(ck[i] >> 10) & 1023u], 1u);
    __syncthreads();

    unsigned int s = 0;
#pragma unroll
    for (int j = 0; j < 4; j++) s += h[1023 - (threadIdx.x * 4 + j)];
    sc[threadIdx.x] = s;
    __syncthreads();
    if (threadIdx.x == 0) {
        unsigned int cum = 0; int seg = 255;
        for (int t = 0; t < 256; t++) {
            if (cum + sc[t] >= r) { seg = t; break; }
            cum += sc[t];
        }
        unsigned int c = cum, s1 = 0;
        for (int j = 0; j < 4; j++) {
            unsigned int d  = 1023 - (seg * 4 + j);
            unsigned int hc = h[d];
            if (c + hc >= r) { s1 = d; break; }
            c += hc;
        }
        res[0] = s1;
        res[1] = r - c;   // rank within sub-bucket
    }
    __syncthreads();
    const unsigned int s1 = res[0];
    const unsigned int r2 = res[1];

    // Phase B: histogram of bits [9:0] for keys matching s1
    for (int i = threadIdx.x; i < 1024; i += 256) h[i] = 0u;
    __syncthreads();
    for (unsigned int i = threadIdx.x; i < n; i += 256) {
        unsigned int kk = ck[i];
        if (((kk >> 10) & 1023u) == s1) atomicAdd(&h[kk & 1023u], 1u);
    }
    __syncthreads();

    s = 0;
#pragma unroll
    for (int j = 0; j < 4; j++) s += h[1023 - (threadIdx.x * 4 + j)];
    sc[threadIdx.x] = s;
    __syncthreads();
    if (threadIdx.x == 0) {
        unsigned int cum = 0; int seg = 255;
        for (int t = 0; t < 256; t++) {
            if (cum + sc[t] >= r2) { seg = t; break; }
            cum += sc[t];
        }
        unsigned int c = cum, d0 = 0;
        for (int j = 0; j < 4; j++) {
            unsigned int d  = 1023 - (seg * 4 + j);
            unsigned int hc = h[d];
            if (c + hc >= r2) { d0 = d; break; }
            c += hc;
        }
        res[2] = (sel << 20) | (s1 << 10) | d0;   // exact key of kth largest
    }
    __syncthreads();
    const unsigned int thr = res[2];

    // Phase C: rewrite kept candidates (others already 0 from k3)
    const int* ci = &g_cidx[b * CAP];
    float* ob = out + (size_t)b * DIM_;
    for (unsigned int i = threadIdx.x; i < n; i += 256) {
        unsigned int kk = ck[i];
        if (kk >= thr) {
            unsigned int bits = (kk & 0x80000000u) ? (kk & 0x7fffffffu) : ~kk;
            ob[ci[i]] = __uint_as_float(bits);
        }
    }
}

// ---------------- launch ------------------------------------------------------
extern "C" void kernel_launch(void* const* d_in, const int* in_sizes, int n_in,
                              void* d_out, int out_size) {
    const float* x   = (const float*)d_in[0];
    float*       out = (float*)d_out;
    (void)in_sizes; (void)n_in; (void)out_size;

    k0_zero<<<64, 256>>>();
    k1_hist<<<dim3(49, 32), 256>>>(x);
    k2_select<<<32, 128>>>();
    k3_mask<<<dim3(98, 8, 32), 256>>>(x, out);
    k4_final<<<32, 256>>>(out);
}

// round 2
// speedup vs baseline: 2.7538x; 2.7538x over previous
#include <cuda_runtime.h>
#include <stdint.h>

// Fixed problem shape: x = (32, 56, 56, 256) fp32, k = ceil(0.2*802816)
#define B_     32
#define HW_    3136
#define C_     256
#define DIM_   802816
#define KRANK  160564u
#define NB     4096
#define CAP    8192         // candidate cap per sample (expected ~30)
#define SBUF   128          // per-block smem candidate buffer in k3
// sampled-histogram targets: expected s_above at true kth = 12544*0.2 = 2508.8
// margins ~= 10 sigma (sigma_rank ~ 2868)
#define T_HI   2040u
#define T_LO   2978u

// ------------------ static device scratch ------------------------------------
__device__ unsigned g_chist[B_ * NB];   // sampled coarse hist (top-12 bits)
__device__ unsigned g_fhist[B_ * NB];   // fine hist over [klo, khi)
__device__ unsigned g_klo[B_], g_khi[B_];
__device__ int      g_shift[B_];
__device__ unsigned g_above[B_];        // exact count of key >= khi
__device__ unsigned g_thrlo[B_], g_thrhi[B_];
__device__ unsigned g_r2[B_];           // rank within threshold fine-bin
__device__ unsigned g_cnt[B_];
__device__ unsigned g_ckey[B_ * CAP];
__device__ int      g_cidx[B_ * CAP];

// order-preserving key: larger float -> larger unsigned
__device__ __forceinline__ unsigned fkey(float f) {
    unsigned u = __float_as_uint(f);
    return (u & 0x80000000u) ? ~u : (u | 0x80000000u);
}
__device__ __forceinline__ float finv(unsigned k) {
    return __uint_as_float((k & 0x80000000u) ? (k & 0x7fffffffu) : ~k);
}

// ------------------ k0: zero scratch ------------------------------------------
__global__ void k0_zero() {
    int stride = gridDim.x * blockDim.x;
    for (int i = blockIdx.x * blockDim.x + threadIdx.x; i < B_ * NB; i += stride)
        g_fhist[i] = 0u;
    if (blockIdx.x == 0 && threadIdx.x < B_) {
        g_cnt[threadIdx.x]   = 0u;
        g_above[threadIdx.x] = 0u;
    }
}

// ------------------ kS: sampled coarse histogram (1 block / sample) ----------
__global__ void kS_sample(const float* __restrict__ x) {
    __shared__ unsigned sh[NB];
    const int b = blockIdx.x, tid = threadIdx.x;
    for (int i = tid; i < NB; i += 256) sh[i] = 0u;
    __syncthreads();
    const float4* p = (const float4*)x + (size_t)b * (DIM_ / 4);
    for (int i = tid; i < 3136; i += 256) {
        float4 v = p[(size_t)i * 63];   // max 3135*63 = 197505 < 200704
        atomicAdd(&sh[fkey(v.x) >> 20], 1u);
        atomicAdd(&sh[fkey(v.y) >> 20], 1u);
        atomicAdd(&sh[fkey(v.z) >> 20], 1u);
        atomicAdd(&sh[fkey(v.w) >> 20], 1u);
    }
    __syncthreads();
    for (int i = tid; i < NB; i += 256) g_chist[b * NB + i] = sh[i];
}

// ------------------ kR: pick conservative key range --------------------------
__global__ void kR_range() {
    __shared__ unsigned sh[NB];
    __shared__ unsigned part[256];
    const int b = blockIdx.x, tid = threadIdx.x;
    for (int i = tid; i < NB; i += 256) sh[i] = g_chist[b * NB + i];
    __syncthreads();
    unsigned s = 0;
#pragma unroll
    for (int j = 0; j < 16; j++) s += sh[NB - 1 - (tid * 16 + j)];
    part[tid] = s;
    __syncthreads();

    if (tid == 0) {
        // d = descending index; cnt(d) = sh[NB-1-d]; CumBefore(d) = sum_{d'<d} cnt
        // dHI = largest d with CumBefore(d) <= T_HI
        int dHI = NB - 1;
        {
            unsigned cc = 0; int d = 0, found = 0;
            for (int sg = 0; sg < 256 && !found; sg++) {
                if (cc + part[sg] <= T_HI) { cc += part[sg]; d += 16; continue; }
                for (int j = 0; j < 16; j++) {
                    unsigned c = sh[NB - 1 - d];
                    if (cc + c > T_HI) { dHI = d; found = 1; break; }
                    cc += c; d++;
                }
            }
        }
        // dLO = smallest d with CumBefore(d) >= T_LO
        int dLO = NB - 1;
        {
            unsigned cc = 0; int d = 0, found = 0;
            for (int sg = 0; sg < 256 && !found; sg++) {
                if (cc < T_LO && cc + part[sg] < T_LO) { cc += part[sg]; d += 16; continue; }
                for (int j = 0; j < 17 && d <= NB; j++) {
                    if (cc >= T_LO) { dLO = d; found = 1; break; }
                    if (d < NB) cc += sh[NB - 1 - d];
                    d++;
                }
            }
        }
        int h = (NB - 1) - dHI;
        int l = NB - dLO;
        if (h >= NB - 1) h = NB - 2;
        if (l < 0) l = 0;
        if (l > h) l = h;
        unsigned klo = (unsigned)l << 20;
        unsigned khi = (unsigned)(h + 1) << 20;
        int nb = h + 1 - l; if (nb < 1) nb = 1;
        int cl2 = (nb <= 1) ? 0 : (32 - __clz(nb - 1));
        g_klo[b] = klo; g_khi[b] = khi; g_shift[b] = 8 + cl2;
    }
}

// ------------------ k1f: full pass — exact above-count + fine histogram ------
__global__ void k1_fine(const float* __restrict__ x) {
    __shared__ unsigned sh[2][NB];
    __shared__ unsigned wsum[8];
    const int b = blockIdx.y, tid = threadIdx.x;
    for (int i = tid; i < 2 * NB; i += 256) ((unsigned*)sh)[i] = 0u;
    __syncthreads();
    const unsigned klo = g_klo[b], khi = g_khi[b];
    const int shf = g_shift[b];
    const float4* p = (const float4*)x + (size_t)b * (DIM_ / 4) + blockIdx.x * 4096;
    unsigned* h = sh[(tid >> 5) & 1];
    unsigned abv = 0;
#pragma unroll
    for (int i = 0; i < 16; i++) {
        float4 v = p[i * 256 + tid];
        unsigned ka = fkey(v.x), kb = fkey(v.y), kc = fkey(v.z), kd = fkey(v.w);
        abv += (ka >= khi) + (kb >= khi) + (kc >= khi) + (kd >= khi);
        if (ka >= klo && ka < khi) atomicAdd(&h[(ka - klo) >> shf], 1u);
        if (kb >= klo && kb < khi) atomicAdd(&h[(kb - klo) >> shf], 1u);
        if (kc >= klo && kc < khi) atomicAdd(&h[(kc - klo) >> shf], 1u);
        if (kd >= klo && kd < khi) atomicAdd(&h[(kd - klo) >> shf], 1u);
    }
    __syncthreads();
    unsigned* gh = &g_fhist[b * NB];
    for (int i = tid; i < NB; i += 256) {
        unsigned t = sh[0][i] + sh[1][i];
        if (t) atomicAdd(&gh[i], t);
    }
#pragma unroll
    for (int off = 16; off; off >>= 1) abv += __shfl_down_sync(~0u, abv, off);
    if ((tid & 31) == 0) wsum[tid >> 5] = abv;
    __syncthreads();
    if (tid == 0) {
        unsigned t = 0;
#pragma unroll
        for (int w = 0; w < 8; w++) t += wsum[w];
        if (t) atomicAdd(&g_above[b], t);
    }
}

// ------------------ k2f: locate exact threshold fine-bin ---------------------
__global__ void k2_sel() {
    __shared__ unsigned sh[NB];
    __shared__ unsigned part[256];
    const int b = blockIdx.x, tid = threadIdx.x;
    for (int i = tid; i < NB; i += 256) sh[i] = g_fhist[b * NB + i];
    __syncthreads();
    unsigned s = 0;
#pragma unroll
    for (int j = 0; j < 16; j++) s += sh[NB - 1 - (tid * 16 + j)];
    part[tid] = s;
    __syncthreads();
    if (tid == 0) {
        unsigned r = KRANK - g_above[b];    // rank within candidate region (>=1)
        unsigned cc = 0; int d = 0, found = 0;
        for (int sg = 0; sg < 256 && !found; sg++) {
            if (cc + part[sg] < r) { cc += part[sg]; d += 16; continue; }
            for (int j = 0; j < 16; j++) {
                unsigned c = sh[NB - 1 - d];
                if (cc + c >= r) { found = 1; break; }
                cc += c; d++;
            }
        }
        int f = (NB - 1) - d;
        unsigned tlo = g_klo[b] + ((unsigned)f << g_shift[b]);
        g_thrlo[b] = tlo;
        g_thrhi[b] = tlo + (1u << g_shift[b]);
        g_r2[b]    = r - cc;
    }
}

// ------------------ k3: transpose + mask + candidate collect -----------------
__global__ void k3_mask(const float* __restrict__ x, float* __restrict__ out) {
    __shared__ float tile[32][33];
    __shared__ unsigned s_key[SBUF];
    __shared__ int      s_idx[SBUF];
    __shared__ int      s_cnt;
    __shared__ unsigned s_base;
    const int b = blockIdx.z, hw0 = blockIdx.x * 32, c0 = blockIdx.y * 32;
    const int tid = threadIdx.x;
    if (tid == 0) s_cnt = 0;
    const unsigned tlo = g_thrlo[b], thi = g_thrhi[b];
    const int tc = tid & 31, tr = tid >> 5;

    const float* xb = x + (size_t)b * DIM_;
#pragma unroll
    for (int i = 0; i < 4; i++) {
        int row = tr + i * 8;
        tile[row][tc] = xb[(size_t)(hw0 + row) * C_ + c0 + tc];
    }
    __syncthreads();

    float* ob = out + (size_t)b * DIM_;
#pragma unroll
    for (int i = 0; i < 4; i++) {
        int   cc = tr + i * 8;
        float v  = tile[tc][cc];
        unsigned kk = fkey(v);
        float o = (kk >= thi) ? v : 0.0f;
        if (kk >= tlo && kk < thi) {
            int p = atomicAdd(&s_cnt, 1);
            if (p < SBUF) {
                s_key[p] = kk;
                s_idx[p] = (c0 + cc) * HW_ + hw0 + tc;
            } else {
                unsigned g = atomicAdd(&g_cnt[b], 1u);
                if (g < CAP) {
                    g_ckey[b * CAP + g] = kk;
                    g_cidx[b * CAP + g] = (c0 + cc) * HW_ + hw0 + tc;
                }
            }
        }
        ob[(size_t)(c0 + cc) * HW_ + hw0 + tc] = o;
    }
    __syncthreads();
    int m = min(s_cnt, SBUF);
    if (tid == 0 && m > 0) s_base = atomicAdd(&g_cnt[b], (unsigned)m);
    __syncthreads();
    for (int i = tid; i < m; i += 256) {
        unsigned g = s_base + i;
        if (g < CAP) {
            g_ckey[b * CAP + g] = s_key[i];
            g_cidx[b * CAP + g] = s_idx[i];
        }
    }
}

// ------------------ k4: exact select among tiny candidate set ----------------
__global__ void k4_final(float* __restrict__ out) {
    __shared__ unsigned sk[CAP];
    __shared__ unsigned s_thr;
    const int b = blockIdx.x, tid = threadIdx.x;
    const unsigned n  = min(g_cnt[b], (unsigned)CAP);
    const unsigned r2 = g_r2[b];
    const unsigned* ck = &g_ckey[b * CAP];
    for (unsigned i = tid; i < n; i += 256) sk[i] = ck[i];
    __syncthreads();
    for (unsigned i = tid; i < n; i += 256) {
        unsigned ki = sk[i], cg = 0, ce = 0;
        for (unsigned j = 0; j < n; j++) {
            unsigned kj = sk[j];
            cg += (kj > ki);
            ce += (kj >= ki);
        }
        if (cg < r2 && ce >= r2) s_thr = ki;   // the exact kth key
    }
    __syncthreads();
    const unsigned thr = s_thr;
    const int* ci = &g_cidx[b * CAP];
    float* ob = out + (size_t)b * DIM_;
    for (unsigned i = tid; i < n; i += 256)
        if (sk[i] >= thr) ob[ci[i]] = finv(sk[i]);
}

// ------------------ launch ----------------------------------------------------
extern "C" void kernel_launch(void* const* d_in, const int* in_sizes, int n_in,
                              void* d_out, int out_size) {
    const float* x   = (const float*)d_in[0];
    float*       out = (float*)d_out;
    (void)in_sizes; (void)n_in; (void)out_size;

    k0_zero <<<64, 256>>>();
    kS_sample<<<32, 256>>>(x);
    kR_range <<<32, 256>>>();
    k1_fine  <<<dim3(49, 32), 256>>>(x);
    k2_sel   <<<32, 256>>>();
    k3_mask  <<<dim3(98, 8, 32), 256>>>(x, out);
    k4_final <<<32, 256>>>(out);
}

// round 3
// speedup vs baseline: 3.6455x; 1.3238x over previous
#include <cuda_runtime.h>
#include <stdint.h>

// Fixed problem shape: x = (32, 56, 56, 256) fp32, k = ceil(0.2*802816)
#define B_     32
#define HW_    3136
#define C_     256
#define DIM_   802816
#define KRANK  160564u
#define NB     4096
#define CAP    8192
#define SBUF   128
// sampled margins: E[count above kth] = 12544*0.2 = 2508.8, sigma ~= 44.8 -> ~10.5 sigma
#define T_HI   2040u
#define T_LO   2978u

// ------------------ static device scratch ------------------------------------
__device__ unsigned g_fhist[B_ * NB];
__device__ unsigned g_klo[B_];
__device__ int      g_shift[B_];
__device__ float    g_flo[B_], g_fhi[B_];     // coarse range as floats (k1)
__device__ float    g_ftlo[B_], g_fthi[B_];   // fine threshold bin as floats (k3)
__device__ unsigned g_above[B_];
__device__ unsigned g_r2[B_];
__device__ unsigned g_cnt[B_];
__device__ unsigned g_ckey[B_ * CAP];
__device__ int      g_cidx[B_ * CAP];

__device__ __forceinline__ unsigned fkey(float f) {
    unsigned u = __float_as_uint(f);
    return (u & 0x80000000u) ? ~u : (u | 0x80000000u);
}
__device__ __forceinline__ float finv(unsigned k) {
    return __uint_as_float((k & 0x80000000u) ? (k & 0x7fffffffu) : ~k);
}

// suffix-sum sh[NB] in place (sh[i] = sum_{j>=i} sh[j]); chunk[256] scratch
__device__ __forceinline__ void suffix_scan(unsigned* sh, unsigned* chunk, int tid) {
    unsigned loc[16];
    unsigned run = 0;
#pragma unroll
    for (int j = 15; j >= 0; j--) { run += sh[tid * 16 + j]; loc[j] = run; }
    chunk[tid] = run;
    __syncthreads();
    for (int s = 1; s < 256; s <<= 1) {
        unsigned v = (tid + s < 256) ? chunk[tid + s] : 0u;
        __syncthreads();
        chunk[tid] += v;
        __syncthreads();
    }
    unsigned off = chunk[tid] - run;   // strict suffix of chunk totals
#pragma unroll
    for (int j = 0; j < 16; j++) sh[tid * 16 + j] = loc[j] + off;
    __syncthreads();
}

// ------------- kSR: zero + sampled coarse hist + parallel range select -------
__global__ void kSR(const float* __restrict__ x) {
    __shared__ unsigned sh[NB];
    __shared__ unsigned chunk[256];
    __shared__ int s_dhi, s_dlo;
    const int b = blockIdx.x, tid = threadIdx.x;
    for (int i = tid; i < NB; i += 256) { g_fhist[b * NB + i] = 0u; sh[i] = 0u; }
    if (tid == 0) { g_cnt[b] = 0u; g_above[b] = 0u; s_dhi = NB - 1; s_dlo = 0; }
    __syncthreads();

    const float4* p = (const float4*)x + (size_t)b * (DIM_ / 4);
    for (int i = tid; i < 3136; i += 256) {
        float4 v = p[(size_t)i * 63];
        atomicAdd(&sh[fkey(v.x) >> 20], 1u);
        atomicAdd(&sh[fkey(v.y) >> 20], 1u);
        atomicAdd(&sh[fkey(v.z) >> 20], 1u);
        atomicAdd(&sh[fkey(v.w) >> 20], 1u);
    }
    __syncthreads();
    suffix_scan(sh, chunk, tid);

#pragma unroll
    for (int j = 0; j < 16; j++) {
        int d = tid * 16 + j;
        unsigned S  = sh[d];
        unsigned Sp = (d > 0) ? sh[d - 1] : 0xffffffffu;
        unsigned Sn = (d < NB - 1) ? sh[d + 1] : 0u;
        if (S <= T_HI && Sp > T_HI) s_dhi = d;      // smallest d with S<=T_HI
        if (S >= T_LO && Sn < T_LO) s_dlo = d;      // largest  d with S>=T_LO
    }
    __syncthreads();
    if (tid == 0) {
        int dh = s_dhi, dl = s_dlo;
        if (dl >= dh) dl = dh - 1;
        if (dl < 0) { dl = 0; if (dh <= dl) dh = 1; }
        unsigned klo = (unsigned)dl << 20, khi = (unsigned)dh << 20;
        int nb = dh - dl;
        int cl2 = (nb <= 1) ? 0 : (32 - __clz(nb - 1));
        g_klo[b]   = klo;
        g_shift[b] = 8 + cl2;
        g_flo[b]   = finv(klo);
        g_fhi[b]   = finv(khi);
    }
}

// ------------- k1: full pass — exact above-count + fine histogram ------------
__global__ void k1_fine(const float* __restrict__ x) {
    __shared__ unsigned sh[2][NB];
    __shared__ unsigned wsum[8];
    const int b = blockIdx.y, tid = threadIdx.x;
    for (int i = tid; i < 2 * NB; i += 256) ((unsigned*)sh)[i] = 0u;
    __syncthreads();
    const float flo = g_flo[b], fhi = g_fhi[b];
    const unsigned klo = g_klo[b];
    const int shf = g_shift[b];
    const float4* p = (const float4*)x + (size_t)b * (DIM_ / 4) + blockIdx.x * 4096;
    unsigned* h = sh[(tid >> 5) & 1];
    unsigned abv = 0;
#pragma unroll
    for (int i = 0; i < 16; i++) {
        float4 v = p[i * 256 + tid];
        abv += (v.x >= fhi) + (v.y >= fhi) + (v.z >= fhi) + (v.w >= fhi);
        if (v.x >= flo && v.x < fhi) atomicAdd(&h[(fkey(v.x) - klo) >> shf], 1u);
        if (v.y >= flo && v.y < fhi) atomicAdd(&h[(fkey(v.y) - klo) >> shf], 1u);
        if (v.z >= flo && v.z < fhi) atomicAdd(&h[(fkey(v.z) - klo) >> shf], 1u);
        if (v.w >= flo && v.w < fhi) atomicAdd(&h[(fkey(v.w) - klo) >> shf], 1u);
    }
    __syncthreads();
    unsigned* gh = &g_fhist[b * NB];
    for (int i = tid; i < NB; i += 256) {
        unsigned t = sh[0][i] + sh[1][i];
        if (t) atomicAdd(&gh[i], t);
    }
#pragma unroll
    for (int off = 16; off; off >>= 1) abv += __shfl_down_sync(~0u, abv, off);
    if ((tid & 31) == 0) wsum[tid >> 5] = abv;
    __syncthreads();
    if (tid == 0) {
        unsigned t = 0;
#pragma unroll
        for (int w = 0; w < 8; w++) t += wsum[w];
        if (t) atomicAdd(&g_above[b], t);
    }
}

// ------------- k2: locate exact threshold fine-bin (parallel) ----------------
__global__ void k2_sel() {
    __shared__ unsigned sh[NB];
    __shared__ unsigned chunk[256];
    __shared__ int s_f;
    __shared__ unsigned s_r2;
    const int b = blockIdx.x, tid = threadIdx.x;
    for (int i = tid; i < NB; i += 256) sh[i] = g_fhist[b * NB + i];
    __syncthreads();
    suffix_scan(sh, chunk, tid);
    const unsigned r = KRANK - g_above[b];
#pragma unroll
    for (int j = 0; j < 16; j++) {
        int d = tid * 16 + j;
        unsigned S  = sh[d];
        unsigned Sn = (d < NB - 1) ? sh[d + 1] : 0u;
        if (S >= r && Sn < r) { s_f = d; s_r2 = r - Sn; }
    }
    __syncthreads();
    if (tid == 0) {
        unsigned tlo = g_klo[b] + ((unsigned)s_f << g_shift[b]);
        g_ftlo[b] = finv(tlo);
        g_fthi[b] = finv(tlo + (1u << g_shift[b]));
        g_r2[b]   = s_r2;
    }
}

// ------------- k3: vectorized 64x64 transpose + mask + candidates ------------
#define TW 65
__global__ void k3_mask(const float* __restrict__ x, float* __restrict__ out) {
    __shared__ float tile[64][TW];
    __shared__ unsigned s_key[SBUF];
    __shared__ int      s_idx[SBUF];
    __shared__ int      s_cnt;
    __shared__ unsigned s_base;
    const int b = blockIdx.z, hw0 = blockIdx.x * 64, c0 = blockIdx.y * 64;
    const int tid = threadIdx.x;
    if (tid == 0) s_cnt = 0;
    const float ftlo = g_ftlo[b], fthi = g_fthi[b];

    const float* xb = x + (size_t)b * DIM_;
    const int f4 = tid & 15, r0 = tid >> 4;
#pragma unroll
    for (int i = 0; i < 4; i++) {
        int row = r0 + i * 16;
        float4 v = *(const float4*)&xb[(size_t)(hw0 + row) * C_ + c0 + f4 * 4];
        tile[row][f4 * 4 + 0] = v.x;
        tile[row][f4 * 4 + 1] = v.y;
        tile[row][f4 * 4 + 2] = v.z;
        tile[row][f4 * 4 + 3] = v.w;
    }
    __syncthreads();

    float* ob = out + (size_t)b * DIM_;
    const int hw4 = tid & 15, cl0 = tid >> 4;
#pragma unroll
    for (int i = 0; i < 4; i++) {
        int cl = cl0 + i * 16;
        float v0 = tile[hw4 * 4 + 0][cl];
        float v1 = tile[hw4 * 4 + 1][cl];
        float v2 = tile[hw4 * 4 + 2][cl];
        float v3 = tile[hw4 * 4 + 3][cl];
        float4 o;
        o.x = (v0 >= fthi) ? v0 : 0.0f;
        o.y = (v1 >= fthi) ? v1 : 0.0f;
        o.z = (v2 >= fthi) ? v2 : 0.0f;
        o.w = (v3 >= fthi) ? v3 : 0.0f;
        int baseidx = (c0 + cl) * HW_ + hw0 + hw4 * 4;
        if (v0 >= ftlo && v0 < fthi) { int p = atomicAdd(&s_cnt, 1); if (p < SBUF) { s_key[p] = fkey(v0); s_idx[p] = baseidx + 0; } }
        if (v1 >= ftlo && v1 < fthi) { int p = atomicAdd(&s_cnt, 1); if (p < SBUF) { s_key[p] = fkey(v1); s_idx[p] = baseidx + 1; } }
        if (v2 >= ftlo && v2 < fthi) { int p = atomicAdd(&s_cnt, 1); if (p < SBUF) { s_key[p] = fkey(v2); s_idx[p] = baseidx + 2; } }
        if (v3 >= ftlo && v3 < fthi) { int p = atomicAdd(&s_cnt, 1); if (p < SBUF) { s_key[p] = fkey(v3); s_idx[p] = baseidx + 3; } }
        *(float4*)&ob[(size_t)(c0 + cl) * HW_ + hw0 + hw4 * 4] = o;
    }
    __syncthreads();
    int m = min(s_cnt, SBUF);
    if (tid == 0 && m > 0) s_base = atomicAdd(&g_cnt[b], (unsigned)m);
    __syncthreads();
    for (int i = tid; i < m; i += 256) {
        unsigned g = s_base + i;
        if (g < CAP) {
            g_ckey[b * CAP + g] = s_key[i];
            g_cidx[b * CAP + g] = s_idx[i];
        }
    }
}

// ------------- k4: exact select among tiny candidate set ---------------------
__global__ void k4_final(float* __restrict__ out) {
    __shared__ unsigned sk[CAP];
    __shared__ unsigned s_thr;
    const int b = blockIdx.x, tid = threadIdx.x;
    const unsigned n  = min(g_cnt[b], (unsigned)CAP);
    const unsigned r2 = g_r2[b];
    const unsigned* ck = &g_ckey[b * CAP];
    for (unsigned i = tid; i < n; i += 256) sk[i] = ck[i];
    __syncthreads();
    for (unsigned i = tid; i < n; i += 256) {
        unsigned ki = sk[i], cg = 0, ce = 0;
        for (unsigned j = 0; j < n; j++) {
            unsigned kj = sk[j];
            cg += (kj > ki);
            ce += (kj >= ki);
        }
        if (cg < r2 && ce >= r2) s_thr = ki;
    }
    __syncthreads();
    const unsigned thr = s_thr;
    const int* ci = &g_cidx[b * CAP];
    float* ob = out + (size_t)b * DIM_;
    for (unsigned i = tid; i < n; i += 256)
        if (sk[i] >= thr) ob[ci[i]] = finv(sk[i]);
}

// ------------------ launch ----------------------------------------------------
extern "C" void kernel_launch(void* const* d_in, const int* in_sizes, int n_in,
                              void* d_out, int out_size) {
    const float* x   = (const float*)d_in[0];
    float*       out = (float*)d_out;
    (void)in_sizes; (void)n_in; (void)out_size;

    kSR     <<<32, 256>>>(x);
    k1_fine <<<dim3(49, 32), 256>>>(x);
    k2_sel  <<<32, 256>>>();
    k3_mask <<<dim3(49, 4, 32), 256>>>(x, out);
    k4_final<<<32, 256>>>(out);
}